// round 1
// baseline (speedup 1.0000x reference)
#include <cuda_runtime.h>
#include <cuda_bf16.h>

#define TT 512
#define H 8

__device__ __forceinline__ float ex2f(float x) {
    float y; asm("ex2.approx.f32 %0, %1;" : "=f"(y) : "f"(x)); return y;
}
__device__ __forceinline__ float rcpf(float x) {
    float y; asm("rcp.approx.f32 %0, %1;" : "=f"(y) : "f"(x)); return y;
}
// a = -z*log2(e)  ->  sigmoid(z)
__device__ __forceinline__ float sigm_s(float a) { return rcpf(1.0f + ex2f(a)); }
// a = -2*z*log2(e) ->  tanh(z)
__device__ __forceinline__ float tanh_s(float a) { return fmaf(2.0f, rcpf(1.0f + ex2f(a)), -1.0f); }

__global__ void __launch_bounds__(128, 1)
lstm2_kernel(const float* __restrict__ x,
             const float* __restrict__ W_ih1, const float* __restrict__ W_hh1,
             const float* __restrict__ b_ih1, const float* __restrict__ b_hh1,
             const float* __restrict__ W_ih2, const float* __restrict__ W_hh2,
             const float* __restrict__ b_ih2, const float* __restrict__ b_hh2,
             const float* __restrict__ W_fc,  const float* __restrict__ b_fc,
             float* __restrict__ out)
{
    const int gtid  = blockIdx.x * blockDim.x + threadIdx.x;
    const int batch = gtid >> 3;
    const int n     = gtid & 7;     // hidden unit owned by this lane
    const unsigned FULL = 0xffffffffu;

    const float NL  = -1.44269504088896340736f;        // -log2(e)  (sigmoid gates)
    const float N2L = -2.88539008177792681472f;        // -2*log2(e) (tanh gate)

    // gate rows (PyTorch order i,f,g,o) for unit n
    const int ri = n, rf = 8 + n, rg = 16 + n, ro = 24 + n;

    // ---- layer-1 weights (input dim = 1), pre-scaled ----
    const float wxi = W_ih1[ri] * NL,  wxf = W_ih1[rf] * NL;
    const float wxg = W_ih1[rg] * N2L, wxo = W_ih1[ro] * NL;
    const float bi1 = (b_ih1[ri] + b_hh1[ri]) * NL;
    const float bf1 = (b_ih1[rf] + b_hh1[rf]) * NL;
    const float bg1 = (b_ih1[rg] + b_hh1[rg]) * N2L;
    const float bo1 = (b_ih1[ro] + b_hh1[ro]) * NL;
    const float bi2 = (b_ih2[ri] + b_hh2[ri]) * NL;
    const float bf2 = (b_ih2[rf] + b_hh2[rf]) * NL;
    const float bg2 = (b_ih2[rg] + b_hh2[rg]) * N2L;
    const float bo2 = (b_ih2[ro] + b_hh2[ro]) * NL;

    float whi1[H], whf1[H], whg1[H], who1[H];
    float wii2[H], wif2[H], wig2[H], wio2[H];
    float whi2[H], whf2[H], whg2[H], who2[H];
#pragma unroll
    for (int k = 0; k < H; ++k) {
        whi1[k] = W_hh1[ri*H + k] * NL;
        whf1[k] = W_hh1[rf*H + k] * NL;
        whg1[k] = W_hh1[rg*H + k] * N2L;
        who1[k] = W_hh1[ro*H + k] * NL;
        wii2[k] = W_ih2[ri*H + k] * NL;
        wif2[k] = W_ih2[rf*H + k] * NL;
        wig2[k] = W_ih2[rg*H + k] * N2L;
        wio2[k] = W_ih2[ro*H + k] * NL;
        whi2[k] = W_hh2[ri*H + k] * NL;
        whf2[k] = W_hh2[rf*H + k] * NL;
        whg2[k] = W_hh2[rg*H + k] * N2L;
        who2[k] = W_hh2[ro*H + k] * NL;
    }

    float h1[H], h2[H];
#pragma unroll
    for (int k = 0; k < H; ++k) { h1[k] = 0.0f; h2[k] = 0.0f; }
    float c1 = 0.0f, c2 = 0.0f;

    const float4* __restrict__ xr = (const float4*)(x + (size_t)batch * TT);
    float4 cur = xr[0];

    for (int t4 = 0; t4 < TT/4; ++t4) {
        // prefetch next chunk while computing current one
        float4 nxt = cur;
        if (t4 + 1 < TT/4) nxt = xr[t4 + 1];

        float xs[4] = {cur.x, cur.y, cur.z, cur.w};
#pragma unroll
        for (int s = 0; s < 4; ++s) {
            const float xt = xs[s];

            // ---------- layer 1 ----------
            float ai = fmaf(wxi, xt, bi1);
            float af = fmaf(wxf, xt, bf1);
            float ag = fmaf(wxg, xt, bg1);
            float ao = fmaf(wxo, xt, bo1);
#pragma unroll
            for (int k = 0; k < H; ++k) {
                ai = fmaf(whi1[k], h1[k], ai);
                af = fmaf(whf1[k], h1[k], af);
                ag = fmaf(whg1[k], h1[k], ag);
                ao = fmaf(who1[k], h1[k], ao);
            }
            const float gi = sigm_s(ai);
            const float gf = sigm_s(af);
            const float go = sigm_s(ao);
            const float gg = tanh_s(ag);
            c1 = fmaf(gf, c1, gi * gg);
            const float h1n = go * tanh_s(c1 * N2L);
#pragma unroll
            for (int k = 0; k < H; ++k) h1[k] = __shfl_sync(FULL, h1n, k, 8);

            // ---------- layer 2 ----------
            float a2i = bi2, a2f = bf2, a2g = bg2, a2o = bo2;
#pragma unroll
            for (int k = 0; k < H; ++k) {
                a2i = fmaf(wii2[k], h1[k], a2i);
                a2f = fmaf(wif2[k], h1[k], a2f);
                a2g = fmaf(wig2[k], h1[k], a2g);
                a2o = fmaf(wio2[k], h1[k], a2o);
            }
#pragma unroll
            for (int k = 0; k < H; ++k) {
                a2i = fmaf(whi2[k], h2[k], a2i);
                a2f = fmaf(whf2[k], h2[k], a2f);
                a2g = fmaf(whg2[k], h2[k], a2g);
                a2o = fmaf(who2[k], h2[k], a2o);
            }
            const float g2i = sigm_s(a2i);
            const float g2f = sigm_s(a2f);
            const float g2o = sigm_s(a2o);
            const float g2g = tanh_s(a2g);
            c2 = fmaf(g2f, c2, g2i * g2g);
            const float h2n = g2o * tanh_s(c2 * N2L);
#pragma unroll
            for (int k = 0; k < H; ++k) h2[k] = __shfl_sync(FULL, h2n, k, 8);
        }
        cur = nxt;
    }

    // ---------- final FC (8 -> 4), lanes 0..3 of each group write ----------
    if (n < 4) {
        float o = b_fc[n];
#pragma unroll
        for (int k = 0; k < H; ++k) o = fmaf(W_fc[n*H + k], h2[k], o);
        out[batch * 4 + n] = o;
    }
}

extern "C" void kernel_launch(void* const* d_in, const int* in_sizes, int n_in,
                              void* d_out, int out_size)
{
    const float* x     = (const float*)d_in[0];
    const float* W_ih1 = (const float*)d_in[1];
    const float* W_hh1 = (const float*)d_in[2];
    const float* b_ih1 = (const float*)d_in[3];
    const float* b_hh1 = (const float*)d_in[4];
    const float* W_ih2 = (const float*)d_in[5];
    const float* W_hh2 = (const float*)d_in[6];
    const float* b_ih2 = (const float*)d_in[7];
    const float* b_hh2 = (const float*)d_in[8];
    const float* W_fc  = (const float*)d_in[9];
    const float* b_fc  = (const float*)d_in[10];
    float* out = (float*)d_out;

    const int B = in_sizes[0] / TT;          // 4096
    const int threads = 128;
    const int blocks  = (B * H) / threads;   // 256

    lstm2_kernel<<<blocks, threads>>>(x, W_ih1, W_hh1, b_ih1, b_hh1,
                                      W_ih2, W_hh2, b_ih2, b_hh2,
                                      W_fc, b_fc, out);
}